// round 3
// baseline (speedup 1.0000x reference)
#include <cuda_runtime.h>
#include <cuda_bf16.h>
#include <cstdint>

// Problem constants (fixed by the reference)
#define EMB    64
#define HEADS  8
#define DIMI   20
#define NQ     4116                  // DIMI + 16*16*16
#define ROWF4  1029                  // 4116 / 4
#define TABR   63                    // 2*CAP - 1
#define INVT   0.125f                // 64^-0.5

#define NPROJ  (3 * HEADS * TABR)    // 1512
#define NCROSS (HEADS * DIMI)        // 160
#define NITEMS (NPROJ + NCROSS)      // 1672

#define CONTENT_BLOCKS 2048          // HEADS * 16 * 16  (one per h,i,j)
#define CHUNK_F4       16464         // 16 rows * 1029 float4
#define ZERO_F4        20580         // 20 rows * 1029 float4

// Precomputed small tables (scaling folded in)
__device__ float g_projH[HEADS * TABR];   // * INVT/3
__device__ float g_projW[HEADS * TABR];
__device__ float g_projD[HEADS * TABR];
__device__ float g_cross[HEADS * DIMI];   // * INVT

// One warp per output scalar: lane c handles elements c and c+32 of the
// 64-length dot product, then butterfly-reduce.
__global__ __launch_bounds__(256)
void prep_kernel(const float* __restrict__ enc_cross,
                 const float* __restrict__ enc_h,
                 const float* __restrict__ enc_w,
                 const float* __restrict__ enc_d,
                 const float* __restrict__ w_cross,
                 const float* __restrict__ w_h,
                 const float* __restrict__ w_w,
                 const float* __restrict__ w_d) {
    const int warp = blockIdx.x * 8 + (threadIdx.x >> 5);
    const int lane = threadIdx.x & 31;
    if (warp >= NITEMS) return;

    const float* vec;
    const float* w;
    float scale;
    float* dst;

    if (warp < NPROJ) {
        const int axis = warp / (HEADS * TABR);
        const int rem  = warp - axis * (HEADS * TABR);
        const int h = rem / TABR, r = rem - h * TABR;
        const float* tab = (axis == 0) ? enc_h : (axis == 1) ? enc_w : enc_d;
        const float* wt  = (axis == 0) ? w_h   : (axis == 1) ? w_w   : w_d;
        float* db        = (axis == 0) ? g_projH : (axis == 1) ? g_projW : g_projD;
        vec = tab + r * EMB;
        w   = wt + h * EMB;
        scale = INVT / 3.0f;
        dst = db + h * TABR + r;
    } else {
        const int rem = warp - NPROJ;
        const int h = rem / DIMI, n = rem - h * DIMI;
        vec = enc_cross + n * EMB;
        w   = w_cross + h * EMB;
        scale = INVT;
        dst = g_cross + h * DIMI + n;
    }

    float s = w[lane] * vec[lane] + w[lane + 32] * vec[lane + 32];
    #pragma unroll
    for (int off = 16; off > 0; off >>= 1)
        s += __shfl_xor_sync(0xffffffffu, s, off);
    if (lane == 0) *dst = s * scale;
}

// Content blocks: one block per (h, i, j) writes 16 consecutive rows
// (k3 = 0..15) = one contiguous 64.3 KB chunk.
// Zero blocks (bid >= CONTENT_BLOCKS): one per head, writes the 20 zero rows.
__global__ __launch_bounds__(256)
void scores_kernel(float* __restrict__ out) {
    const int b = blockIdx.x;
    const int t = threadIdx.x;

    if (b >= CONTENT_BLOCKS) {
        // zero rows: head hb, rows q = 0..19
        const int hb = b - CONTENT_BLOCKS;
        float4* __restrict__ dst =
            reinterpret_cast<float4*>(out + (size_t)hb * NQ * NQ);
        const float4 z = make_float4(0.f, 0.f, 0.f, 0.f);
        #pragma unroll 4
        for (int g = t; g < ZERO_F4; g += 256) dst[g] = z;
        return;
    }

    const int h = b >> 8;
    const int i = (b >> 4) & 15;
    const int j = b & 15;

    __shared__ float sa[16], sb[16], sd[TABR], scr[DIMI];
    if (t < 16)            sa[t]      = g_projH[h * TABR + t - i + 31];
    else if (t < 32)       sb[t - 16] = g_projW[h * TABR + (t - 16) - j + 31];
    else if (t < 32 + TABR) sd[t - 32] = g_projD[h * TABR + (t - 32)];
    else if (t < 32 + TABR + DIMI) scr[t - 32 - TABR] = g_cross[h * DIMI + (t - 32 - TABR)];
    __syncthreads();

    const int base_row = h * NQ + DIMI + i * 256 + j * 16;
    float4* __restrict__ dst = reinterpret_cast<float4*>(out + (size_t)base_row * NQ);

    #pragma unroll 4
    for (int g = t; g < CHUNK_F4; g += 256) {
        const int r = g / ROWF4;            // k3 digit of this row (0..15)
        const int f = g - r * ROWF4;        // float4 index within row
        float4 v;
        if (f < 5) {
            v.x = scr[4 * f + 0];
            v.y = scr[4 * f + 1];
            v.z = scr[4 * f + 2];
            v.w = scr[4 * f + 3];
        } else {
            const int scol = 4 * f - DIMI;   // multiple of 4
            const int l  = scol >> 8;
            const int m  = (scol >> 4) & 15;
            const int n0 = (scol & 15) - r + 31;
            const float base = sa[l] + sb[m];
            v.x = base + sd[n0 + 0];
            v.y = base + sd[n0 + 1];
            v.z = base + sd[n0 + 2];
            v.w = base + sd[n0 + 3];
        }
        dst[g] = v;
    }
}

extern "C" void kernel_launch(void* const* d_in, const int* in_sizes, int n_in,
                              void* d_out, int out_size) {
    const float* enc_cross = (const float*)d_in[0];
    const float* enc_h     = (const float*)d_in[1];
    const float* enc_w     = (const float*)d_in[2];
    const float* enc_d     = (const float*)d_in[3];
    const float* w_cross   = (const float*)d_in[4];
    const float* w_h       = (const float*)d_in[5];
    const float* w_w       = (const float*)d_in[6];
    const float* w_d       = (const float*)d_in[7];
    float* out = (float*)d_out;

    prep_kernel<<<(NITEMS + 7) / 8, 256>>>(enc_cross, enc_h, enc_w, enc_d,
                                           w_cross, w_h, w_w, w_d);
    scores_kernel<<<CONTENT_BLOCKS + HEADS, 256>>>(out);
}